// round 1
// baseline (speedup 1.0000x reference)
#include <cuda_runtime.h>

// Problem constants
#define NQ      4096        // B*T = 4*1024 queries
#define NK      65536       // memory bank size
#define DIM     128
#define TOPK    32
#define SPLITS  16
#define KEYS_PER_SPLIT (NK / SPLITS)   // 4096
#define QTILE   128
#define KCHUNK  64
#define NCHUNKS (KEYS_PER_SPLIT / KCHUNK)  // 64

// smem strides (floats), chosen for conflict-free stores / aligned float4 loads
#define QSTRIDE 132
#define KSTRIDE 72
#define SMEM_BYTES ((DIM * QSTRIDE + DIM * KSTRIDE) * 4)   // 104448 B

#define CAND_PER_QS  256                      // 8 tx-threads * 32 each
#define CAND_PER_Q   (SPLITS * CAND_PER_QS)   // 4096

#define NEG_INF (-3.402823466e38f)

// Scratch: candidate (score, index) pairs. 4096 queries * 4096 candidates.
__device__ float g_cand_s[(size_t)NQ * CAND_PER_Q];
__device__ int   g_cand_i[(size_t)NQ * CAND_PER_Q];

// ---------------------------------------------------------------------------
// Kernel 1: fused scoring + per-thread top-32 selection.
// Grid: 32 q-tiles * 16 key-splits = 512 blocks, 256 threads.
// Block tile: 128 queries x 4096 keys. Thread micro-tile: 4q x 8k.
// Thread (ty = t>>3 in 0..31, tx = t&7): queries ty*4..ty*4+3,
// keys (chunk*64 + tx*8 .. +7) over 64 chunks => 512 keys per query per thread.
// ---------------------------------------------------------------------------
__global__ void __launch_bounds__(256, 1)
score_select_kernel(const float* __restrict__ q, const float* __restrict__ keys)
{
    extern __shared__ float smem[];
    float* qs = smem;                       // [DIM][QSTRIDE]  (d-major, transposed)
    float* ks = smem + DIM * QSTRIDE;       // [DIM][KSTRIDE]

    const int qtile = blockIdx.x / SPLITS;
    const int split = blockIdx.x % SPLITS;
    const int q0    = qtile * QTILE;
    const int n0    = split * KEYS_PER_SPLIT;
    const int t     = threadIdx.x;
    const int ty    = t >> 3;   // 0..31 (query group)
    const int tx    = t & 7;    // 0..7  (key group)

    // --- load Q tile transposed into smem: qs[d][lq] ---
    // mapping: warp covers 32 consecutive lq at fixed d4 -> conflict-free smem stores
#pragma unroll
    for (int it = 0; it < 16; ++it) {
        int idx = it * 256 + t;           // 0..4095
        int lq  = idx & 127;
        int d4  = idx >> 7;               // 0..31
        float4 v = *(const float4*)&q[(size_t)(q0 + lq) * DIM + d4 * 4];
        qs[(d4 * 4 + 0) * QSTRIDE + lq] = v.x;
        qs[(d4 * 4 + 1) * QSTRIDE + lq] = v.y;
        qs[(d4 * 4 + 2) * QSTRIDE + lq] = v.z;
        qs[(d4 * 4 + 3) * QSTRIDE + lq] = v.w;
    }

    // --- per-thread top-32 state for 4 queries (local memory arrays) ---
    float bs[4 * TOPK];
    int   bi[4 * TOPK];
    float bmin[4];
    int   bminp[4];
#pragma unroll
    for (int i = 0; i < 4 * TOPK; ++i) { bs[i] = NEG_INF; bi[i] = 0; }
#pragma unroll
    for (int i = 0; i < 4; ++i) { bmin[i] = NEG_INF; bminp[i] = 0; }

    for (int c = 0; c < NCHUNKS; ++c) {
        __syncthreads();   // previous chunk consumed
        // --- load 64-key chunk transposed: ks[d][lk] ---
#pragma unroll
        for (int it = 0; it < 8; ++it) {
            int idx = it * 256 + t;       // 0..2047
            int lk  = idx & 63;
            int d4  = idx >> 6;           // 0..31
            float4 v = *(const float4*)&keys[(size_t)(n0 + c * KCHUNK + lk) * DIM + d4 * 4];
            ks[(d4 * 4 + 0) * KSTRIDE + lk] = v.x;
            ks[(d4 * 4 + 1) * KSTRIDE + lk] = v.y;
            ks[(d4 * 4 + 2) * KSTRIDE + lk] = v.z;
            ks[(d4 * 4 + 3) * KSTRIDE + lk] = v.w;
        }
        __syncthreads();

        // --- 4q x 8k register micro-tile GEMM over d = 0..127 ---
        float acc[4][8];
#pragma unroll
        for (int i = 0; i < 4; ++i)
#pragma unroll
            for (int j = 0; j < 8; ++j) acc[i][j] = 0.0f;

#pragma unroll 8
        for (int d = 0; d < DIM; ++d) {
            const float4 qv = *(const float4*)(qs + d * QSTRIDE + (ty << 2));
            const float4 ka = *(const float4*)(ks + d * KSTRIDE + (tx << 3));
            const float4 kb = *(const float4*)(ks + d * KSTRIDE + (tx << 3) + 4);
            const float qq[4] = {qv.x, qv.y, qv.z, qv.w};
            const float kk[8] = {ka.x, ka.y, ka.z, ka.w, kb.x, kb.y, kb.z, kb.w};
#pragma unroll
            for (int i = 0; i < 4; ++i)
#pragma unroll
                for (int j = 0; j < 8; ++j)
                    acc[i][j] = fmaf(qq[i], kk[j], acc[i][j]);
        }

        // --- selection: replace-min top-32 per (thread, query) ---
        const int nbase = n0 + c * KCHUNK + (tx << 3);
#pragma unroll
        for (int i = 0; i < 4; ++i) {
#pragma unroll
            for (int j = 0; j < 8; ++j) {
                float s = acc[i][j];
                if (s > bmin[i]) {      // strict > : keeps earlier (lower) index on ties
                    int p = bminp[i];
                    bs[i * TOPK + p] = s;
                    bi[i * TOPK + p] = nbase + j;
                    float m = bs[i * TOPK];
                    int mp = 0;
#pragma unroll
                    for (int u = 1; u < TOPK; ++u) {
                        float v = bs[i * TOPK + u];
                        if (v < m) { m = v; mp = u; }
                    }
                    bmin[i] = m; bminp[i] = mp;
                }
            }
        }
    }

    // --- dump candidates to global scratch ---
#pragma unroll
    for (int i = 0; i < 4; ++i) {
        int gq = q0 + (ty << 2) + i;
        size_t base = ((size_t)gq * SPLITS + split) * CAND_PER_QS + tx * TOPK;
#pragma unroll
        for (int j = 0; j < TOPK; ++j) {
            g_cand_s[base + j] = bs[i * TOPK + j];
            g_cand_i[base + j] = bi[i * TOPK + j];
        }
    }
}

// ---------------------------------------------------------------------------
// Kernel 2: per-query merge (bitonic sort of 4096 candidates, exact jax
// top_k tie semantics: descending score, ascending index on ties) + gather.
// Grid: 4096 blocks (one per query), 256 threads.
// ---------------------------------------------------------------------------
__global__ void __launch_bounds__(256)
merge_gather_kernel(const float* __restrict__ keys,
                    const float* __restrict__ values,
                    float* __restrict__ outK,
                    float* __restrict__ outV)
{
    __shared__ float ss[CAND_PER_Q];
    __shared__ int   sx[CAND_PER_Q];

    const int qidx = blockIdx.x;
    const int t = threadIdx.x;
    const size_t cbase = (size_t)qidx * CAND_PER_Q;

    for (int i = t; i < CAND_PER_Q; i += 256) {
        ss[i] = g_cand_s[cbase + i];
        sx[i] = g_cand_i[cbase + i];
    }

    // bitonic sort, final order: descending score (ties: ascending index)
    for (int k2 = 2; k2 <= CAND_PER_Q; k2 <<= 1) {
        for (int j = k2 >> 1; j > 0; j >>= 1) {
            __syncthreads();
            for (int i = t; i < CAND_PER_Q; i += 256) {
                int l = i ^ j;
                if (l > i) {
                    float si_s = ss[i], sl_s = ss[l];
                    int   si_i = sx[i], sl_i = sx[l];
                    bool l_before_i = (sl_s > si_s) || (sl_s == si_s && sl_i < si_i);
                    bool i_before_l = (si_s > sl_s) || (si_s == sl_s && si_i < sl_i);
                    bool up = ((i & k2) == 0);           // descending sub-sequence
                    bool doswap = up ? l_before_i : i_before_l;
                    if (doswap) {
                        ss[i] = sl_s; ss[l] = si_s;
                        sx[i] = sl_i; sx[l] = si_i;
                    }
                }
            }
        }
    }
    __syncthreads();

    // gather: top-32 rows of keys -> outK, values -> outV  (float4 vectorized)
    for (int i = t; i < TOPK * (DIM / 4); i += 256) {   // 1024 float4 per tensor
        int row  = i >> 5;          // 0..31
        int col4 = i & 31;          // 0..31
        int n = sx[row];
        size_t src = (size_t)n * DIM + col4 * 4;
        size_t dst = ((size_t)qidx * TOPK + row) * DIM + col4 * 4;
        *(float4*)&outK[dst] = *(const float4*)&keys[src];
        *(float4*)&outV[dst] = *(const float4*)&values[src];
    }
}

// ---------------------------------------------------------------------------
extern "C" void kernel_launch(void* const* d_in, const int* in_sizes, int n_in,
                              void* d_out, int out_size)
{
    const float* q      = (const float*)d_in[0];   // [4,1024,128]
    const float* keys   = (const float*)d_in[1];   // [65536,128]
    const float* values = (const float*)d_in[2];   // [65536,128]
    float* outK = (float*)d_out;                         // [4,1024,32,128]
    float* outV = outK + (size_t)NQ * TOPK * DIM;        // second tensor

    cudaFuncSetAttribute(score_select_kernel,
                         cudaFuncAttributeMaxDynamicSharedMemorySize, SMEM_BYTES);

    score_select_kernel<<<(NQ / QTILE) * SPLITS, 256, SMEM_BYTES>>>(q, keys);
    merge_gather_kernel<<<NQ, 256>>>(keys, values, outK, outV);
}